// round 3
// baseline (speedup 1.0000x reference)
#include <cuda_runtime.h>
#include <cuda_bf16.h>
#include <math.h>

// ---------------- problem constants ----------------
#define NG    128
#define NPG   256
#define DF    128
#define KBINS 16
#define NSLOT (2*NG)
#define SMS   256              // smem row stride (floats) for k-major operand tile

#define INV_TEMP 2.0f
#define LAMBDA   0.1f
#define GA (-0.82073318f)      // a*log2(e), a = -0.5/(0.9375^2)

// smem layout (bytes)
#define OFF_A    0
#define OFF_D    (DF*SMS*4)                 // 131072
#define OFF_SQ   (OFF_D + 3*128*128*2)      // 131072+98304 = 229376
#define OFF_MISC (OFF_SQ + 1024)            // 230400
#define SMEM_TOT (OFF_MISC + 576)           // 230976

// ---------------- device scratch ----------------
__device__ float g_hist[NSLOT * KBINS];     // unnormalized per-slot hists
__device__ float g_rowloss[NSLOT];
__device__ float g_znT[DF * NSLOT];         // [k][row]
__device__ float g_znR[NSLOT * DF];         // [row][k]

// ---------------- f32x2 helpers ----------------
static __device__ __forceinline__ unsigned long long pk2(float lo, float hi) {
    unsigned long long r;
    asm("mov.b64 %0, {%1, %2};" : "=l"(r)
        : "r"(__float_as_uint(lo)), "r"(__float_as_uint(hi)));
    return r;
}
static __device__ __forceinline__ unsigned long long ffma2(
        unsigned long long a, unsigned long long b, unsigned long long c) {
    unsigned long long r;
    asm("fma.rn.f32x2 %0, %1, %2, %3;" : "=l"(r) : "l"(a), "l"(b), "l"(c));
    return r;
}
static __device__ __forceinline__ unsigned long long mul2(
        unsigned long long a, unsigned long long b) {
    unsigned long long r;
    asm("mul.rn.f32x2 %0, %1, %2;" : "=l"(r) : "l"(a), "l"(b));
    return r;
}
static __device__ __forceinline__ void up2(unsigned long long v, float& lo, float& hi) {
    unsigned ulo, uhi;
    asm("mov.b64 {%0, %1}, %2;" : "=r"(ulo), "=r"(uhi) : "l"(v));
    lo = __uint_as_float(ulo);
    hi = __uint_as_float(uhi);
}
static __device__ __forceinline__ float ex2f(float x) {
    float r;
    asm("ex2.approx.f32 %0, %1;" : "=f"(r) : "f"(x));
    return r;
}

// ---------------- kernel 1: znorm ----------------
__global__ __launch_bounds__(256) void k_znorm(const float* __restrict__ z1,
                                               const float* __restrict__ z2) {
    int t = threadIdx.x;
    const float* zr = (t < NG) ? (z1 + (size_t)t * DF) : (z2 + (size_t)(t - NG) * DF);
    float ss = 0.f;
    for (int k = 0; k < DF; k++) { float v = zr[k]; ss += v * v; }
    float inv = 1.0f / (sqrtf(ss) + 1e-8f);
    for (int k = 0; k < DF; k++) {
        float v = zr[k] * inv;
        g_znT[k * NSLOT + t] = v;
        g_znR[t * DF + k]    = v;
    }
}

// ---------------- kernel 2: fused transpose + pairdist + soft histogram ----------------
__global__ __launch_bounds__(256, 1) void k_fused(const float* __restrict__ H1,
                                                  const float* __restrict__ H2) {
    extern __shared__ char smraw[];
    float* A = (float*)(smraw + OFF_A);                        // [128][256] k-major
    __nv_bfloat16* Dsm = (__nv_bfloat16*)(smraw + OFF_D);      // [3][128][128]
    float* sq   = (float*)(smraw + OFF_SQ);                    // [256]
    float* misc = (float*)(smraw + OFF_MISC);                  // rsum[8], total[1], hsm[8][16]
    float* rsum = misc;
    float* hsm  = misc + 16;                                   // 8*16

    int s = blockIdx.x;
    int g = s & (NG - 1);
    const float* H = (s < NG ? H1 : H2) + (size_t)g * NPG * DF;
    int tid = threadIdx.x;

    // ---- phase 0: transposed load (stage via buffer in D region) ----
    {
        float (*stage)[33] = (float (*)[33])(smraw + OFF_D);
        int tx = tid & 31;
        int tw = tid >> 5;
        for (int t = 0; t < 32; t++) {
            int tr = t >> 2;           // node tile
            int tc = t & 3;            // k tile
            #pragma unroll
            for (int j = 0; j < 4; j++) {
                int y = tw + 8 * j;
                stage[y][tx] = H[(size_t)(tr * 32 + y) * DF + tc * 32 + tx];
            }
            __syncthreads();
            #pragma unroll
            for (int j = 0; j < 4; j++) {
                int y = tw + 8 * j;
                A[(tc * 32 + y) * SMS + tr * 32 + tx] = stage[tx][y];
            }
            __syncthreads();
        }
    }

    // ---- phase 1: squared norms ----
    {
        float ssq = 0.f;
        for (int k = 0; k < DF; k++) { float v = A[k * SMS + tid]; ssq += v * v; }
        sq[tid] = ssq;
    }
    __syncthreads();

    // ---- phase 2: GEMM (3 quadrants), distances -> bf16 smem, weighted sum ----
    int tx = tid & 15, ty = tid >> 4;
    float tsum = 0.f;

    #pragma unroll 1
    for (int m = 0; m < 3; m++) {
        int rb = (m == 2) ? 1 : 0;
        int cb = (m >= 1) ? 1 : 0;
        float w = (m == 1) ? 2.0f : 1.0f;
        int row0 = rb * 128 + ty * 8;
        int col0 = cb * 128 + tx * 8;

        unsigned long long acc[8][4];
        #pragma unroll
        for (int r = 0; r < 8; r++)
            #pragma unroll
            for (int j = 0; j < 4; j++) acc[r][j] = 0ULL;

        #pragma unroll 1
        for (int k = 0; k < DF; k++) {
            const float* rp = A + k * SMS;
            float4 a0 = *(const float4*)(rp + row0);
            float4 a1 = *(const float4*)(rp + row0 + 4);
            ulonglong2 bq0 = *(const ulonglong2*)(rp + col0);
            ulonglong2 bq1 = *(const ulonglong2*)(rp + col0 + 4);
            unsigned long long pb0 = bq0.x, pb1 = bq0.y, pb2 = bq1.x, pb3 = bq1.y;
            float av[8] = {a0.x, a0.y, a0.z, a0.w, a1.x, a1.y, a1.z, a1.w};
            #pragma unroll
            for (int r = 0; r < 8; r++) {
                unsigned long long pa = pk2(av[r], av[r]);
                acc[r][0] = ffma2(pa, pb0, acc[r][0]);
                acc[r][1] = ffma2(pa, pb1, acc[r][1]);
                acc[r][2] = ffma2(pa, pb2, acc[r][2]);
                acc[r][3] = ffma2(pa, pb3, acc[r][3]);
            }
        }

        float sqj[8];
        #pragma unroll
        for (int c = 0; c < 8; c++) sqj[c] = sq[col0 + c];

        #pragma unroll
        for (int r = 0; r < 8; r++) {
            int lrow = ty * 8 + r;
            float sqi = sq[row0 + r];
            float dots[8];
            up2(acc[r][0], dots[0], dots[1]);
            up2(acc[r][1], dots[2], dots[3]);
            up2(acc[r][2], dots[4], dots[5]);
            up2(acc[r][3], dots[6], dots[7]);
            float o[8];
            #pragma unroll
            for (int c = 0; c < 8; c++) {
                float d2 = sqi + sqj[c] - 2.0f * dots[c];
                float dd = sqrtf(fmaxf(d2, 0.0f) + 1e-12f);
                o[c] = dd;
                tsum += w * dd;
            }
            __nv_bfloat162 b0 = __floats2bfloat162_rn(o[0], o[1]);
            __nv_bfloat162 b1 = __floats2bfloat162_rn(o[2], o[3]);
            __nv_bfloat162 b2 = __floats2bfloat162_rn(o[4], o[5]);
            __nv_bfloat162 b3 = __floats2bfloat162_rn(o[6], o[7]);
            uint4 st;
            st.x = *(unsigned*)&b0; st.y = *(unsigned*)&b1;
            st.z = *(unsigned*)&b2; st.w = *(unsigned*)&b3;
            *(uint4*)(Dsm + m * 16384 + lrow * 128 + tx * 8) = st;
        }
    }

    // ---- phase 3: reduce tsum -> mean -> sbin ----
    #pragma unroll
    for (int off = 16; off > 0; off >>= 1)
        tsum += __shfl_down_sync(0xffffffffu, tsum, off);
    if ((tid & 31) == 0) rsum[tid >> 5] = tsum;
    __syncthreads();
    if (tid == 0) {
        float tot = 0.f;
        #pragma unroll
        for (int wI = 0; wI < 8; wI++) tot += rsum[wI];
        rsum[0] = tot;
    }
    __syncthreads();
    float mean = rsum[0] * (1.0f / 65536.0f);
    float sbin = 5.0f / (mean + 1e-8f);
    __syncthreads();

    // ---- phase 4: histogram from bf16 smem (Gaussian recurrence, f32x2) ----
    float su_s = ex2f(2.0f * GA);
    unsigned long long su2 = pk2(su_s, su_s);

    unsigned long long hacc[KBINS];
    #pragma unroll
    for (int k = 0; k < KBINS; k++) hacc[k] = 0ULL;

    #pragma unroll 1
    for (int m = 0; m < 3; m++) {
        float wq = (m == 1) ? 2.0f : 1.0f;
        unsigned long long wq2 = pk2(wq, wq);
        const __nv_bfloat16* base = Dsm + m * 16384 + (ty * 8) * 128 + tx * 8;
        #pragma unroll 1
        for (int r = 0; r < 8; r++) {
            uint4 v = *(const uint4*)(base + r * 128);
            unsigned pw[4] = {v.x, v.y, v.z, v.w};
            #pragma unroll
            for (int e = 0; e < 4; e++) {
                __nv_bfloat162 h = *(__nv_bfloat162*)&pw[e];
                float2 f = __bfloat1622float2(h);
                float p0 = f.x * sbin, p1 = f.y * sbin;
                float t0 = p0 - 7.0f, t1 = p1 - 7.0f;
                float w70 = ex2f((GA * t0) * t0);
                float w71 = ex2f((GA * t1) * t1);
                float ru0 = ex2f(fmaf(-2.0f * GA, p0, 15.0f * GA));
                float ru1 = ex2f(fmaf(-2.0f * GA, p1, 15.0f * GA));
                float rd0 = ex2f(fmaf( 2.0f * GA, p0, -13.0f * GA));
                float rd1 = ex2f(fmaf( 2.0f * GA, p1, -13.0f * GA));
                unsigned long long w7 = pk2(w70, w71);
                unsigned long long ru = pk2(ru0, ru1);
                unsigned long long rd = pk2(rd0, rd1);

                hacc[7] = ffma2(w7, wq2, hacc[7]);
                unsigned long long wu = w7;
                #pragma unroll
                for (int k = 8; k < 16; k++) {
                    wu = mul2(wu, ru);
                    hacc[k] = ffma2(wu, wq2, hacc[k]);
                    ru = mul2(ru, su2);
                }
                unsigned long long wd = w7;
                #pragma unroll
                for (int k = 6; k >= 0; k--) {
                    wd = mul2(wd, rd);
                    hacc[k] = ffma2(wd, wq2, hacc[k]);
                    rd = mul2(rd, su2);
                }
            }
        }
    }

    // ---- phase 5: block-reduce hist -> global ----
    #pragma unroll
    for (int k = 0; k < KBINS; k++) {
        float lo, hi;
        up2(hacc[k], lo, hi);
        float v = lo + hi;
        #pragma unroll
        for (int off = 16; off > 0; off >>= 1)
            v += __shfl_down_sync(0xffffffffu, v, off);
        if ((tid & 31) == 0) hsm[(tid >> 5) * KBINS + k] = v;
    }
    __syncthreads();
    if (tid < KBINS) {
        float t = 0.f;
        #pragma unroll
        for (int wI = 0; wI < 8; wI++) t += hsm[wI * KBINS + tid];
        g_hist[s * KBINS + tid] = t;
    }
}

// ---------------- kernel 3: NT-Xent (one block per row) ----------------
__global__ __launch_bounds__(256) void k_ntxent() {
    __shared__ float zrow[DF];
    __shared__ float red[256];
    __shared__ float slab;

    int i = blockIdx.x;
    int j = threadIdx.x;

    if (j < DF) zrow[j] = g_znR[(size_t)i * DF + j];
    __syncthreads();

    float acc = 0.f;
    #pragma unroll 4
    for (int k = 0; k < DF; k++)
        acc += zrow[k] * g_znT[k * NSLOT + j];
    float sim = acc * INV_TEMP;
    if (j == i) sim = -1e9f;

    int label = (i < NG) ? i + NG : i - NG;
    if (j == label) slab = sim;

    // max reduce
    red[j] = sim;
    __syncthreads();
    for (int st = 128; st > 0; st >>= 1) {
        if (j < st) red[j] = fmaxf(red[j], red[j + st]);
        __syncthreads();
    }
    float rmax = red[0];
    __syncthreads();

    red[j] = __expf(sim - rmax);
    __syncthreads();
    for (int st = 128; st > 0; st >>= 1) {
        if (j < st) red[j] += red[j + st];
        __syncthreads();
    }
    if (j == 0) {
        float lse = rmax + logf(red[0]);
        g_rowloss[i] = lse - slab;
    }
}

// ---------------- kernel 4: final scalar ----------------
__global__ __launch_bounds__(256) void k_final(float* __restrict__ out) {
    __shared__ float red[256];
    __shared__ float tsave;
    int t = threadIdx.x;

    float v = 0.f;
    if (t < NG) {
        float h1[KBINS], h2[KBINS];
        float sA = 0.f, sB = 0.f;
        #pragma unroll
        for (int k = 0; k < KBINS; k++) {
            float a = g_hist[t * KBINS + k];
            float b = g_hist[(t + NG) * KBINS + k];
            h1[k] = a; h2[k] = b; sA += a; sB += b;
        }
        float iA = 1.f / (sA + 1e-8f), iB = 1.f / (sB + 1e-8f);
        float m = 0.f;
        #pragma unroll
        for (int k = 0; k < KBINS; k++) {
            float d = h1[k] * iA - h2[k] * iB;
            m += d * d;
        }
        v = m * (1.0f / KBINS);
    }
    red[t] = v;
    __syncthreads();
    for (int st = 128; st > 0; st >>= 1) {
        if (t < st) red[t] += red[t + st];
        __syncthreads();
    }
    if (t == 0) tsave = red[0];
    __syncthreads();

    red[t] = g_rowloss[t];
    __syncthreads();
    for (int st = 128; st > 0; st >>= 1) {
        if (t < st) red[t] += red[t + st];
        __syncthreads();
    }
    if (t == 0) {
        float topo = tsave * (1.0f / NG);
        float ntx  = red[0] * (1.0f / NSLOT);
        out[0] = LAMBDA * (topo + ntx);
    }
}

// ---------------- launcher ----------------
extern "C" void kernel_launch(void* const* d_in, const int* in_sizes, int n_in,
                              void* d_out, int out_size) {
    const float* H1 = (const float*)d_in[0];
    const float* H2 = (const float*)d_in[2];
    const float* z1 = (const float*)d_in[4];
    const float* z2 = (const float*)d_in[5];
    float* out = (float*)d_out;

    cudaFuncSetAttribute(k_fused, cudaFuncAttributeMaxDynamicSharedMemorySize, SMEM_TOT);

    k_znorm<<<1, 256>>>(z1, z2);
    k_fused<<<NSLOT, 256, SMEM_TOT>>>(H1, H2);
    k_ntxent<<<NSLOT, 256>>>();
    k_final<<<1, 256>>>(out);
}

// round 4
// speedup vs baseline: 1.0036x; 1.0036x over previous
#include <cuda_runtime.h>
#include <cuda_bf16.h>
#include <math.h>

// ---------------- problem constants ----------------
#define NG    128
#define NPG   256
#define DF    128
#define KBINS 16
#define NSLOT (2*NG)
#define SMS   256              // smem row stride (floats) for k-major operand tile

#define INV_TEMP 2.0f
#define LAMBDA   0.1f
#define GA (-0.82073318f)      // a*log2(e), a = -0.5/(0.9375^2)

// smem layout (bytes)
#define OFF_A    0
#define OFF_D    (DF*SMS*4)                 // 131072
#define OFF_SQ   (OFF_D + 3*128*128*2)      // 131072+98304 = 229376
#define OFF_MISC (OFF_SQ + 1024)            // 230400
#define SMEM_TOT (OFF_MISC + 576)           // 230976

// ---------------- device scratch ----------------
__device__ float g_hist[NSLOT * KBINS];     // unnormalized per-slot hists
__device__ float g_rowloss[NSLOT];
__device__ float g_znT[DF * NSLOT];         // [k][row]
__device__ float g_znR[NSLOT * DF];         // [row][k]

// ---------------- f32x2 helpers ----------------
static __device__ __forceinline__ unsigned long long pk2(float lo, float hi) {
    unsigned long long r;
    asm("mov.b64 %0, {%1, %2};" : "=l"(r)
        : "r"(__float_as_uint(lo)), "r"(__float_as_uint(hi)));
    return r;
}
static __device__ __forceinline__ unsigned long long ffma2(
        unsigned long long a, unsigned long long b, unsigned long long c) {
    unsigned long long r;
    asm("fma.rn.f32x2 %0, %1, %2, %3;" : "=l"(r) : "l"(a), "l"(b), "l"(c));
    return r;
}
static __device__ __forceinline__ unsigned long long mul2(
        unsigned long long a, unsigned long long b) {
    unsigned long long r;
    asm("mul.rn.f32x2 %0, %1, %2;" : "=l"(r) : "l"(a), "l"(b));
    return r;
}
static __device__ __forceinline__ void up2(unsigned long long v, float& lo, float& hi) {
    unsigned ulo, uhi;
    asm("mov.b64 {%0, %1}, %2;" : "=r"(ulo), "=r"(uhi) : "l"(v));
    lo = __uint_as_float(ulo);
    hi = __uint_as_float(uhi);
}
static __device__ __forceinline__ float ex2f(float x) {
    float r;
    asm("ex2.approx.f32 %0, %1;" : "=f"(r) : "f"(x));
    return r;
}

// ---------------- kernel 1: znorm ----------------
__global__ __launch_bounds__(256) void k_znorm(const float* __restrict__ z1,
                                               const float* __restrict__ z2) {
    int t = threadIdx.x;
    const float* zr = (t < NG) ? (z1 + (size_t)t * DF) : (z2 + (size_t)(t - NG) * DF);
    float ss = 0.f;
    for (int k = 0; k < DF; k++) { float v = zr[k]; ss += v * v; }
    float inv = 1.0f / (sqrtf(ss) + 1e-8f);
    for (int k = 0; k < DF; k++) {
        float v = zr[k] * inv;
        g_znT[k * NSLOT + t] = v;
        g_znR[t * DF + k]    = v;
    }
}

// ---------------- kernel 2: fused transpose + pairdist + soft histogram ----------------
__global__ __launch_bounds__(256, 1) void k_fused(const float* __restrict__ H1,
                                                  const float* __restrict__ H2) {
    extern __shared__ char smraw[];
    float* A = (float*)(smraw + OFF_A);                        // [128][256] k-major
    __nv_bfloat16* Dsm = (__nv_bfloat16*)(smraw + OFF_D);      // [3][128][128]
    float* sq   = (float*)(smraw + OFF_SQ);                    // [256]
    float* misc = (float*)(smraw + OFF_MISC);                  // rsum[8], total[1], hsm[8][16]
    float* rsum = misc;
    float* hsm  = misc + 16;                                   // 8*16

    int s = blockIdx.x;
    int g = s & (NG - 1);
    const float* H = (s < NG ? H1 : H2) + (size_t)g * NPG * DF;
    int tid = threadIdx.x;

    // ---- phase 0: transposed load (stage via buffer in D region) ----
    {
        float (*stage)[33] = (float (*)[33])(smraw + OFF_D);
        int tx = tid & 31;
        int tw = tid >> 5;
        for (int t = 0; t < 32; t++) {
            int tr = t >> 2;           // node tile
            int tc = t & 3;            // k tile
            #pragma unroll
            for (int j = 0; j < 4; j++) {
                int y = tw + 8 * j;
                stage[y][tx] = H[(size_t)(tr * 32 + y) * DF + tc * 32 + tx];
            }
            __syncthreads();
            #pragma unroll
            for (int j = 0; j < 4; j++) {
                int y = tw + 8 * j;
                A[(tc * 32 + y) * SMS + tr * 32 + tx] = stage[tx][y];
            }
            __syncthreads();
        }
    }

    // ---- phase 1: squared norms ----
    {
        float ssq = 0.f;
        for (int k = 0; k < DF; k++) { float v = A[k * SMS + tid]; ssq += v * v; }
        sq[tid] = ssq;
    }
    __syncthreads();

    // ---- phase 2: GEMM (3 quadrants), distances -> bf16 smem, weighted sum ----
    int tx = tid & 15, ty = tid >> 4;
    float tsum = 0.f;

    #pragma unroll 1
    for (int m = 0; m < 3; m++) {
        int rb = (m == 2) ? 1 : 0;
        int cb = (m >= 1) ? 1 : 0;
        float w = (m == 1) ? 2.0f : 1.0f;
        int row0 = rb * 128 + ty * 8;
        int col0 = cb * 128 + tx * 8;

        unsigned long long acc[8][4];
        #pragma unroll
        for (int r = 0; r < 8; r++)
            #pragma unroll
            for (int j = 0; j < 4; j++) acc[r][j] = 0ULL;

        #pragma unroll 1
        for (int k = 0; k < DF; k++) {
            const float* rp = A + k * SMS;
            float4 a0 = *(const float4*)(rp + row0);
            float4 a1 = *(const float4*)(rp + row0 + 4);
            ulonglong2 bq0 = *(const ulonglong2*)(rp + col0);
            ulonglong2 bq1 = *(const ulonglong2*)(rp + col0 + 4);
            unsigned long long pb0 = bq0.x, pb1 = bq0.y, pb2 = bq1.x, pb3 = bq1.y;
            float av[8] = {a0.x, a0.y, a0.z, a0.w, a1.x, a1.y, a1.z, a1.w};
            #pragma unroll
            for (int r = 0; r < 8; r++) {
                unsigned long long pa = pk2(av[r], av[r]);
                acc[r][0] = ffma2(pa, pb0, acc[r][0]);
                acc[r][1] = ffma2(pa, pb1, acc[r][1]);
                acc[r][2] = ffma2(pa, pb2, acc[r][2]);
                acc[r][3] = ffma2(pa, pb3, acc[r][3]);
            }
        }

        float sqj[8];
        #pragma unroll
        for (int c = 0; c < 8; c++) sqj[c] = sq[col0 + c];

        #pragma unroll
        for (int r = 0; r < 8; r++) {
            int lrow = ty * 8 + r;
            float sqi = sq[row0 + r];
            float dots[8];
            up2(acc[r][0], dots[0], dots[1]);
            up2(acc[r][1], dots[2], dots[3]);
            up2(acc[r][2], dots[4], dots[5]);
            up2(acc[r][3], dots[6], dots[7]);
            float o[8];
            #pragma unroll
            for (int c = 0; c < 8; c++) {
                float d2 = sqi + sqj[c] - 2.0f * dots[c];
                float dd = sqrtf(fmaxf(d2, 0.0f) + 1e-12f);
                o[c] = dd;
                tsum += w * dd;
            }
            __nv_bfloat162 b0 = __floats2bfloat162_rn(o[0], o[1]);
            __nv_bfloat162 b1 = __floats2bfloat162_rn(o[2], o[3]);
            __nv_bfloat162 b2 = __floats2bfloat162_rn(o[4], o[5]);
            __nv_bfloat162 b3 = __floats2bfloat162_rn(o[6], o[7]);
            uint4 st;
            st.x = *(unsigned*)&b0; st.y = *(unsigned*)&b1;
            st.z = *(unsigned*)&b2; st.w = *(unsigned*)&b3;
            *(uint4*)(Dsm + m * 16384 + lrow * 128 + tx * 8) = st;
        }
    }

    // ---- phase 3: reduce tsum -> mean -> sbin ----
    #pragma unroll
    for (int off = 16; off > 0; off >>= 1)
        tsum += __shfl_down_sync(0xffffffffu, tsum, off);
    if ((tid & 31) == 0) rsum[tid >> 5] = tsum;
    __syncthreads();
    if (tid == 0) {
        float tot = 0.f;
        #pragma unroll
        for (int wI = 0; wI < 8; wI++) tot += rsum[wI];
        rsum[0] = tot;
    }
    __syncthreads();
    float mean = rsum[0] * (1.0f / 65536.0f);
    float sbin = 5.0f / (mean + 1e-8f);
    __syncthreads();

    // ---- phase 4: histogram from bf16 smem (Gaussian recurrence, f32x2) ----
    float su_s = ex2f(2.0f * GA);
    unsigned long long su2 = pk2(su_s, su_s);

    unsigned long long hacc[KBINS];
    #pragma unroll
    for (int k = 0; k < KBINS; k++) hacc[k] = 0ULL;

    #pragma unroll 1
    for (int m = 0; m < 3; m++) {
        float wq = (m == 1) ? 2.0f : 1.0f;
        unsigned long long wq2 = pk2(wq, wq);
        const __nv_bfloat16* base = Dsm + m * 16384 + (ty * 8) * 128 + tx * 8;
        #pragma unroll 1
        for (int r = 0; r < 8; r++) {
            uint4 v = *(const uint4*)(base + r * 128);
            unsigned pw[4] = {v.x, v.y, v.z, v.w};
            #pragma unroll
            for (int e = 0; e < 4; e++) {
                __nv_bfloat162 h = *(__nv_bfloat162*)&pw[e];
                float2 f = __bfloat1622float2(h);
                float p0 = f.x * sbin, p1 = f.y * sbin;
                float t0 = p0 - 7.0f, t1 = p1 - 7.0f;
                float w70 = ex2f((GA * t0) * t0);
                float w71 = ex2f((GA * t1) * t1);
                float ru0 = ex2f(fmaf(-2.0f * GA, p0, 15.0f * GA));
                float ru1 = ex2f(fmaf(-2.0f * GA, p1, 15.0f * GA));
                float rd0 = ex2f(fmaf( 2.0f * GA, p0, -13.0f * GA));
                float rd1 = ex2f(fmaf( 2.0f * GA, p1, -13.0f * GA));
                unsigned long long w7 = pk2(w70, w71);
                unsigned long long ru = pk2(ru0, ru1);
                unsigned long long rd = pk2(rd0, rd1);

                hacc[7] = ffma2(w7, wq2, hacc[7]);
                unsigned long long wu = w7;
                #pragma unroll
                for (int k = 8; k < 16; k++) {
                    wu = mul2(wu, ru);
                    hacc[k] = ffma2(wu, wq2, hacc[k]);
                    ru = mul2(ru, su2);
                }
                unsigned long long wd = w7;
                #pragma unroll
                for (int k = 6; k >= 0; k--) {
                    wd = mul2(wd, rd);
                    hacc[k] = ffma2(wd, wq2, hacc[k]);
                    rd = mul2(rd, su2);
                }
            }
        }
    }

    // ---- phase 5: block-reduce hist -> global ----
    #pragma unroll
    for (int k = 0; k < KBINS; k++) {
        float lo, hi;
        up2(hacc[k], lo, hi);
        float v = lo + hi;
        #pragma unroll
        for (int off = 16; off > 0; off >>= 1)
            v += __shfl_down_sync(0xffffffffu, v, off);
        if ((tid & 31) == 0) hsm[(tid >> 5) * KBINS + k] = v;
    }
    __syncthreads();
    if (tid < KBINS) {
        float t = 0.f;
        #pragma unroll
        for (int wI = 0; wI < 8; wI++) t += hsm[wI * KBINS + tid];
        g_hist[s * KBINS + tid] = t;
    }
}

// ---------------- kernel 3: NT-Xent (one block per row) ----------------
__global__ __launch_bounds__(256) void k_ntxent() {
    __shared__ float zrow[DF];
    __shared__ float red[256];
    __shared__ float slab;

    int i = blockIdx.x;
    int j = threadIdx.x;

    if (j < DF) zrow[j] = g_znR[(size_t)i * DF + j];
    __syncthreads();

    float acc = 0.f;
    #pragma unroll 4
    for (int k = 0; k < DF; k++)
        acc += zrow[k] * g_znT[k * NSLOT + j];
    float sim = acc * INV_TEMP;
    if (j == i) sim = -1e9f;

    int label = (i < NG) ? i + NG : i - NG;
    if (j == label) slab = sim;

    // max reduce
    red[j] = sim;
    __syncthreads();
    for (int st = 128; st > 0; st >>= 1) {
        if (j < st) red[j] = fmaxf(red[j], red[j + st]);
        __syncthreads();
    }
    float rmax = red[0];
    __syncthreads();

    red[j] = __expf(sim - rmax);
    __syncthreads();
    for (int st = 128; st > 0; st >>= 1) {
        if (j < st) red[j] += red[j + st];
        __syncthreads();
    }
    if (j == 0) {
        float lse = rmax + logf(red[0]);
        g_rowloss[i] = lse - slab;
    }
}

// ---------------- kernel 4: final scalar ----------------
__global__ __launch_bounds__(256) void k_final(float* __restrict__ out) {
    __shared__ float red[256];
    __shared__ float tsave;
    int t = threadIdx.x;

    float v = 0.f;
    if (t < NG) {
        float h1[KBINS], h2[KBINS];
        float sA = 0.f, sB = 0.f;
        #pragma unroll
        for (int k = 0; k < KBINS; k++) {
            float a = g_hist[t * KBINS + k];
            float b = g_hist[(t + NG) * KBINS + k];
            h1[k] = a; h2[k] = b; sA += a; sB += b;
        }
        float iA = 1.f / (sA + 1e-8f), iB = 1.f / (sB + 1e-8f);
        float m = 0.f;
        #pragma unroll
        for (int k = 0; k < KBINS; k++) {
            float d = h1[k] * iA - h2[k] * iB;
            m += d * d;
        }
        v = m * (1.0f / KBINS);
    }
    red[t] = v;
    __syncthreads();
    for (int st = 128; st > 0; st >>= 1) {
        if (t < st) red[t] += red[t + st];
        __syncthreads();
    }
    if (t == 0) tsave = red[0];
    __syncthreads();

    red[t] = g_rowloss[t];
    __syncthreads();
    for (int st = 128; st > 0; st >>= 1) {
        if (t < st) red[t] += red[t + st];
        __syncthreads();
    }
    if (t == 0) {
        float topo = tsave * (1.0f / NG);
        float ntx  = red[0] * (1.0f / NSLOT);
        out[0] = LAMBDA * (topo + ntx);
    }
}

// ---------------- launcher ----------------
extern "C" void kernel_launch(void* const* d_in, const int* in_sizes, int n_in,
                              void* d_out, int out_size) {
    const float* H1 = (const float*)d_in[0];
    const float* H2 = (const float*)d_in[2];
    const float* z1 = (const float*)d_in[4];
    const float* z2 = (const float*)d_in[5];
    float* out = (float*)d_out;

    cudaFuncSetAttribute(k_fused, cudaFuncAttributeMaxDynamicSharedMemorySize, SMEM_TOT);

    k_znorm<<<1, 256>>>(z1, z2);
    k_fused<<<NSLOT, 256, SMEM_TOT>>>(H1, H2);
    k_ntxent<<<NSLOT, 256>>>();
    k_final<<<1, 256>>>(out);
}

// round 6
// speedup vs baseline: 1.5301x; 1.5247x over previous
#include <cuda_runtime.h>
#include <cuda_bf16.h>
#include <math.h>
#include <stdint.h>

// ---------------- problem constants ----------------
#define NG    128
#define NPG   256
#define DF    128
#define KBINS 16
#define NSLOT 256

#define INV_TEMP 2.0f
#define LAMBDA   0.1f
#define GA (-0.82073318f)      // a*log2(e), a = -0.5/(0.9375^2)

// ---------------- device scratch ----------------
__device__ __nv_bfloat16 g_Dbf[(size_t)NSLOT * NPG * NPG];   // 33.5MB distances
__device__ float g_sumPart[NSLOT * 4];
__device__ float g_hpart[NSLOT * 4 * KBINS];
__device__ float g_rowloss[NSLOT];
__device__ float g_znT[DF * NSLOT];
__device__ float g_znR[NSLOT * DF];

// ---------------- helpers ----------------
static __device__ __forceinline__ uint32_t smem_u32(const void* p) {
    uint32_t a;
    asm("{ .reg .u64 t; cvta.to.shared.u64 t, %1; cvt.u32.u64 %0, t; }" : "=r"(a) : "l"(p));
    return a;
}
static __device__ __forceinline__ unsigned long long pk2(float lo, float hi) {
    unsigned long long r;
    asm("mov.b64 %0, {%1, %2};" : "=l"(r) : "r"(__float_as_uint(lo)), "r"(__float_as_uint(hi)));
    return r;
}
static __device__ __forceinline__ unsigned long long mul2(unsigned long long a, unsigned long long b) {
    unsigned long long r;
    asm("mul.rn.f32x2 %0, %1, %2;" : "=l"(r) : "l"(a), "l"(b));
    return r;
}
static __device__ __forceinline__ unsigned long long add2(unsigned long long a, unsigned long long b) {
    unsigned long long r;
    asm("add.rn.f32x2 %0, %1, %2;" : "=l"(r) : "l"(a), "l"(b));
    return r;
}
static __device__ __forceinline__ void up2(unsigned long long v, float& lo, float& hi) {
    unsigned ulo, uhi;
    asm("mov.b64 {%0, %1}, %2;" : "=r"(ulo), "=r"(uhi) : "l"(v));
    lo = __uint_as_float(ulo); hi = __uint_as_float(uhi);
}
static __device__ __forceinline__ float ex2f(float x) {
    float r; asm("ex2.approx.f32 %0, %1;" : "=f"(r) : "f"(x)); return r;
}
static __device__ __forceinline__ void ldmx4(uint32_t& r0, uint32_t& r1, uint32_t& r2, uint32_t& r3, uint32_t addr) {
    asm volatile("ldmatrix.sync.aligned.m8n8.x4.shared.b16 {%0,%1,%2,%3}, [%4];"
                 : "=r"(r0), "=r"(r1), "=r"(r2), "=r"(r3) : "r"(addr));
}
static __device__ __forceinline__ void mma16816(float* c, uint32_t a0, uint32_t a1, uint32_t a2, uint32_t a3,
                                                uint32_t b0, uint32_t b1) {
    asm volatile("mma.sync.aligned.m16n8k16.row.col.f32.bf16.bf16.f32 "
                 "{%0,%1,%2,%3}, {%4,%5,%6,%7}, {%8,%9}, {%0,%1,%2,%3};"
                 : "+f"(c[0]), "+f"(c[1]), "+f"(c[2]), "+f"(c[3])
                 : "r"(a0), "r"(a1), "r"(a2), "r"(a3), "r"(b0), "r"(b1));
}
// tile layout: [row][128 bf16] = 256B/row = 16 units of 16B; phys unit = u ^ (row&7)
static __device__ __forceinline__ uint32_t tphys(int row, int kbyte) {
    return (uint32_t)(row * 256 + ((((kbyte >> 4) ^ (row & 7)) << 4) | (kbyte & 15)));
}

// ---------------- kernel 1: znorm ----------------
__global__ __launch_bounds__(256) void k_znorm(const float* __restrict__ z1,
                                               const float* __restrict__ z2) {
    int t = threadIdx.x;
    const float* zr = (t < NG) ? (z1 + (size_t)t * DF) : (z2 + (size_t)(t - NG) * DF);
    float ss = 0.f;
    for (int k = 0; k < DF; k++) { float v = zr[k]; ss += v * v; }
    float inv = 1.0f / (sqrtf(ss) + 1e-8f);
    for (int k = 0; k < DF; k++) {
        float v = zr[k] * inv;
        g_znT[k * NSLOT + t] = v;
        g_znR[t * DF + k]    = v;
    }
}

// ---------------- kernel 2: HMMA Gram -> distances (bf16) ----------------
// grid = NSLOT*4; block (s, q): quadrant rows qr..qr+127, cols qc..qc+127
__global__ __launch_bounds__(256, 2) void k_gemm(const float* __restrict__ H1,
                                                 const float* __restrict__ H2) {
    extern __shared__ char smraw[];                 // As 32KB | Bs 32KB
    __shared__ float sqA[128], sqB[128], rsum[8];

    int bx = blockIdx.x;
    int s = bx >> 2, q = bx & 3;
    int qr = (q >> 1) * 128, qc = (q & 1) * 128;
    int g = s & (NG - 1);
    const float* H = (s < NG ? H1 : H2) + (size_t)g * NPG * DF;
    int tid = threadIdx.x;
    int lane = tid & 31;
    int wid = tid >> 5;

    // ---- load both tiles as bf16 swizzled smem; sq from the same bf16 values ----
    #pragma unroll
    for (int t = 0; t < 2; t++) {
        int qoff = t ? qc : qr;
        char* base = smraw + t * 32768;
        float* sqdst = t ? sqB : sqA;
        #pragma unroll
        for (int it = 0; it < 8; it++) {
            int i = tid + it * 256;
            int row = i >> 4, u = i & 15;           // row 0..127, 16B unit 0..15
            const float4* p = (const float4*)(H + (size_t)(qoff + row) * DF + u * 8);
            float4 v0 = p[0], v1 = p[1];
            __nv_bfloat162 h0 = __floats2bfloat162_rn(v0.x, v0.y);
            __nv_bfloat162 h1 = __floats2bfloat162_rn(v0.z, v0.w);
            __nv_bfloat162 h2 = __floats2bfloat162_rn(v1.x, v1.y);
            __nv_bfloat162 h3 = __floats2bfloat162_rn(v1.z, v1.w);
            uint4 st;
            st.x = *(uint32_t*)&h0; st.y = *(uint32_t*)&h1;
            st.z = *(uint32_t*)&h2; st.w = *(uint32_t*)&h3;
            *(uint4*)(base + tphys(row, u * 16)) = st;
            float2 f0 = __bfloat1622float2(h0), f1 = __bfloat1622float2(h1);
            float2 f2 = __bfloat1622float2(h2), f3 = __bfloat1622float2(h3);
            float ssq = f0.x * f0.x + f0.y * f0.y + f1.x * f1.x + f1.y * f1.y
                      + f2.x * f2.x + f2.y * f2.y + f3.x * f3.x + f3.y * f3.y;
            ssq += __shfl_down_sync(0xffffffffu, ssq, 8, 16);
            ssq += __shfl_down_sync(0xffffffffu, ssq, 4, 16);
            ssq += __shfl_down_sync(0xffffffffu, ssq, 2, 16);
            ssq += __shfl_down_sync(0xffffffffu, ssq, 1, 16);
            if ((lane & 15) == 0) sqdst[row] = ssq;
        }
    }
    __syncthreads();

    // ---- GEMM: warp tile 32x64; warps 4x2 over 128x128 ----
    int wr = (wid >> 1) * 32;
    int wc = (wid & 1) * 64;
    uint32_t smbA = smem_u32(smraw);
    uint32_t smbB = smbA + 32768;

    float acc[2][8][4];
    #pragma unroll
    for (int mt = 0; mt < 2; mt++)
        #pragma unroll
        for (int nt = 0; nt < 8; nt++)
            #pragma unroll
            for (int e = 0; e < 4; e++) acc[mt][nt][e] = 0.f;

    int gA = lane >> 3;                 // ldmatrix address group
    int arow_off = (gA & 1) * 8 + (lane & 7);
    int akb_off  = (gA >> 1) * 16;
    int brow_off = (gA >> 1) * 8 + (lane & 7);
    int bkb_off  = (gA & 1) * 16;

    #pragma unroll 1
    for (int ks = 0; ks < 8; ks++) {
        int kb = ks * 32;
        uint32_t a[2][4];
        #pragma unroll
        for (int mt = 0; mt < 2; mt++) {
            uint32_t addr = smbA + tphys(wr + mt * 16 + arow_off, kb + akb_off);
            ldmx4(a[mt][0], a[mt][1], a[mt][2], a[mt][3], addr);
        }
        uint32_t b[8][2];
        #pragma unroll
        for (int np = 0; np < 4; np++) {
            uint32_t addr = smbB + tphys(wc + np * 16 + brow_off, kb + bkb_off);
            uint32_t r0, r1, r2, r3;
            ldmx4(r0, r1, r2, r3, addr);
            b[np * 2][0] = r0; b[np * 2][1] = r1;
            b[np * 2 + 1][0] = r2; b[np * 2 + 1][1] = r3;
        }
        #pragma unroll
        for (int mt = 0; mt < 2; mt++)
            #pragma unroll
            for (int nt = 0; nt < 8; nt++)
                mma16816(acc[mt][nt], a[mt][0], a[mt][1], a[mt][2], a[mt][3],
                         b[nt][0], b[nt][1]);
    }

    // ---- epilogue: d = sqrt(sqi + sqj - 2G), bf16 store, partial sum ----
    float tsum = 0.f;
    int lr = lane >> 2;                 // 0..7
    int lc = (lane & 3) * 2;
    __nv_bfloat16* Dslot = g_Dbf + ((size_t)s << 16);

    #pragma unroll
    for (int mt = 0; mt < 2; mt++) {
        int r0l = wr + mt * 16 + lr;
        float sa0 = sqA[r0l], sa1 = sqA[r0l + 8];
        int gr0 = qr + r0l;
        #pragma unroll
        for (int nt = 0; nt < 8; nt++) {
            int cl = wc + nt * 8 + lc;
            float sb0 = sqB[cl], sb1 = sqB[cl + 1];
            float* c = acc[mt][nt];
            float d00 = sqrtf(fmaxf(sa0 + sb0 - 2.0f * c[0], 0.0f) + 1e-12f);
            float d01 = sqrtf(fmaxf(sa0 + sb1 - 2.0f * c[1], 0.0f) + 1e-12f);
            float d10 = sqrtf(fmaxf(sa1 + sb0 - 2.0f * c[2], 0.0f) + 1e-12f);
            float d11 = sqrtf(fmaxf(sa1 + sb1 - 2.0f * c[3], 0.0f) + 1e-12f);
            tsum += (d00 + d01) + (d10 + d11);
            __nv_bfloat162 p0 = __floats2bfloat162_rn(d00, d01);
            __nv_bfloat162 p1 = __floats2bfloat162_rn(d10, d11);
            *(uint32_t*)(Dslot + ((size_t)gr0 << 8) + qc + cl)       = *(uint32_t*)&p0;
            *(uint32_t*)(Dslot + ((size_t)(gr0 + 8) << 8) + qc + cl) = *(uint32_t*)&p1;
        }
    }

    // deterministic block reduction
    #pragma unroll
    for (int off = 16; off > 0; off >>= 1)
        tsum += __shfl_down_sync(0xffffffffu, tsum, off);
    if (lane == 0) rsum[wid] = tsum;
    __syncthreads();
    if (tid == 0) {
        float tot = 0.f;
        #pragma unroll
        for (int w = 0; w < 8; w++) tot += rsum[w];
        g_sumPart[bx] = tot;
    }
}

// ---------------- kernel 3: soft histogram (recurrence, f32x2) ----------------
__global__ __launch_bounds__(256) void k_hist() {
    int s    = blockIdx.x >> 2;
    int part = blockIdx.x & 3;
    int tid  = threadIdx.x;
    const uint4* Du4 = (const uint4*)(g_Dbf + ((size_t)s << 16));

    float sumD = g_sumPart[s * 4] + g_sumPart[s * 4 + 1]
               + g_sumPart[s * 4 + 2] + g_sumPart[s * 4 + 3];
    float mean = sumD * (1.0f / 65536.0f);
    float sbin = 5.0f / (mean + 1e-8f);

    float su_s = ex2f(2.0f * GA);
    unsigned long long su2 = pk2(su_s, su_s);

    unsigned long long acc[KBINS];
    #pragma unroll
    for (int k = 0; k < KBINS; k++) acc[k] = 0ULL;

    #pragma unroll 1
    for (int it = 0; it < 8; it++) {
        uint4 v = Du4[part * 2048 + it * 256 + tid];   // 8 bf16 distances
        uint32_t pw[4] = {v.x, v.y, v.z, v.w};
        #pragma unroll
        for (int e = 0; e < 4; e++) {
            float2 f = __bfloat1622float2(*(__nv_bfloat162*)&pw[e]);
            float p0 = f.x * sbin, p1 = f.y * sbin;
            float t0 = p0 - 7.0f, t1 = p1 - 7.0f;
            float w70 = ex2f((GA * t0) * t0);
            float w71 = ex2f((GA * t1) * t1);
            float ru0 = ex2f(fmaf(-2.0f * GA, p0, 15.0f * GA));
            float ru1 = ex2f(fmaf(-2.0f * GA, p1, 15.0f * GA));
            float rd0 = ex2f(fmaf( 2.0f * GA, p0, -13.0f * GA));
            float rd1 = ex2f(fmaf( 2.0f * GA, p1, -13.0f * GA));
            unsigned long long w7 = pk2(w70, w71);
            unsigned long long ru = pk2(ru0, ru1);
            unsigned long long rd = pk2(rd0, rd1);

            acc[7] = add2(w7, acc[7]);
            unsigned long long wu = w7;
            #pragma unroll
            for (int k = 8; k < 16; k++) {
                wu = mul2(wu, ru);
                acc[k] = add2(wu, acc[k]);
                ru = mul2(ru, su2);
            }
            unsigned long long wd = w7;
            #pragma unroll
            for (int k = 6; k >= 0; k--) {
                wd = mul2(wd, rd);
                acc[k] = add2(wd, acc[k]);
                rd = mul2(rd, su2);
            }
        }
    }

    __shared__ float hsm[8][KBINS];
    #pragma unroll
    for (int k = 0; k < KBINS; k++) {
        float lo, hi;
        up2(acc[k], lo, hi);
        float v = lo + hi;
        #pragma unroll
        for (int off = 16; off > 0; off >>= 1)
            v += __shfl_down_sync(0xffffffffu, v, off);
        if ((tid & 31) == 0) hsm[tid >> 5][k] = v;
    }
    __syncthreads();
    if (tid < KBINS) {
        float t = 0.f;
        #pragma unroll
        for (int w = 0; w < 8; w++) t += hsm[w][tid];
        g_hpart[(s * 4 + part) * KBINS + tid] = t;
    }
}

// ---------------- kernel 4: NT-Xent (one block per row) ----------------
__global__ __launch_bounds__(256) void k_ntxent() {
    __shared__ float zrow[DF];
    __shared__ float red[256];
    __shared__ float slab;

    int i = blockIdx.x;
    int j = threadIdx.x;

    if (j < DF) zrow[j] = g_znR[(size_t)i * DF + j];
    __syncthreads();

    float acc = 0.f;
    #pragma unroll 4
    for (int k = 0; k < DF; k++)
        acc += zrow[k] * g_znT[k * NSLOT + j];
    float sim = acc * INV_TEMP;
    if (j == i) sim = -1e9f;

    int label = (i < NG) ? i + NG : i - NG;
    if (j == label) slab = sim;

    red[j] = sim;
    __syncthreads();
    for (int st = 128; st > 0; st >>= 1) {
        if (j < st) red[j] = fmaxf(red[j], red[j + st]);
        __syncthreads();
    }
    float rmax = red[0];
    __syncthreads();

    red[j] = __expf(sim - rmax);
    __syncthreads();
    for (int st = 128; st > 0; st >>= 1) {
        if (j < st) red[j] += red[j + st];
        __syncthreads();
    }
    if (j == 0) {
        float lse = rmax + logf(red[0]);
        g_rowloss[i] = lse - slab;
    }
}

// ---------------- kernel 5: merge hists + final scalar ----------------
__global__ __launch_bounds__(256) void k_final(float* __restrict__ out) {
    __shared__ float red[256];
    __shared__ float tsave;
    int t = threadIdx.x;

    float v = 0.f;
    if (t < NG) {
        float h1[KBINS], h2[KBINS];
        float sA = 0.f, sB = 0.f;
        #pragma unroll
        for (int k = 0; k < KBINS; k++) {
            float a = 0.f, b = 0.f;
            #pragma unroll
            for (int p = 0; p < 4; p++) {
                a += g_hpart[(t * 4 + p) * KBINS + k];
                b += g_hpart[((t + NG) * 4 + p) * KBINS + k];
            }
            h1[k] = a; h2[k] = b; sA += a; sB += b;
        }
        float iA = 1.f / (sA + 1e-8f), iB = 1.f / (sB + 1e-8f);
        float m = 0.f;
        #pragma unroll
        for (int k = 0; k < KBINS; k++) {
            float d = h1[k] * iA - h2[k] * iB;
            m += d * d;
        }
        v = m * (1.0f / KBINS);
    }
    red[t] = v;
    __syncthreads();
    for (int st = 128; st > 0; st >>= 1) {
        if (t < st) red[t] += red[t + st];
        __syncthreads();
    }
    if (t == 0) tsave = red[0];
    __syncthreads();

    red[t] = g_rowloss[t];
    __syncthreads();
    for (int st = 128; st > 0; st >>= 1) {
        if (t < st) red[t] += red[t + st];
        __syncthreads();
    }
    if (t == 0) {
        float topo = tsave * (1.0f / NG);
        float ntx  = red[0] * (1.0f / NSLOT);
        out[0] = LAMBDA * (topo + ntx);
    }
}

// ---------------- launcher ----------------
extern "C" void kernel_launch(void* const* d_in, const int* in_sizes, int n_in,
                              void* d_out, int out_size) {
    const float* H1 = (const float*)d_in[0];
    const float* H2 = (const float*)d_in[2];
    const float* z1 = (const float*)d_in[4];
    const float* z2 = (const float*)d_in[5];
    float* out = (float*)d_out;

    cudaFuncSetAttribute(k_gemm, cudaFuncAttributeMaxDynamicSharedMemorySize, 65536);

    k_znorm<<<1, 256>>>(z1, z2);
    k_gemm<<<NSLOT * 4, 256, 65536>>>(H1, H2);
    k_hist<<<NSLOT * 4, 256>>>();
    k_ntxent<<<NSLOT, 256>>>();
    k_final<<<1, 256>>>(out);
}

// round 7
// speedup vs baseline: 3.0360x; 1.9841x over previous
#include <cuda_runtime.h>
#include <cuda_bf16.h>
#include <math.h>
#include <stdint.h>

// ---------------- problem constants ----------------
#define NG    128
#define NPG   256
#define DF    128
#define KBINS 16
#define NSLOT 256

#define INV_TEMP 2.0f
#define LAMBDA   0.1f
#define GA (-0.82073318f)      // a*log2(e), a = -0.5/(0.9375^2)

// ---------------- device scratch ----------------
__device__ __nv_bfloat16 g_Dbf[(size_t)NSLOT * NPG * NPG];   // distances (3 of 4 quadrants)
__device__ float g_sumPart[NSLOT * 3];
__device__ float g_hpart[NSLOT * 3 * KBINS];
__device__ float g_rowloss[NSLOT];
__device__ float g_znT[DF * NSLOT];
__device__ float g_znR[NSLOT * DF];

// ---------------- helpers ----------------
static __device__ __forceinline__ uint32_t smem_u32(const void* p) {
    uint32_t a;
    asm("{ .reg .u64 t; cvta.to.shared.u64 t, %1; cvt.u32.u64 %0, t; }" : "=r"(a) : "l"(p));
    return a;
}
static __device__ __forceinline__ unsigned long long pk2(float lo, float hi) {
    unsigned long long r;
    asm("mov.b64 %0, {%1, %2};" : "=l"(r) : "r"(__float_as_uint(lo)), "r"(__float_as_uint(hi)));
    return r;
}
static __device__ __forceinline__ unsigned long long mul2(unsigned long long a, unsigned long long b) {
    unsigned long long r;
    asm("mul.rn.f32x2 %0, %1, %2;" : "=l"(r) : "l"(a), "l"(b));
    return r;
}
static __device__ __forceinline__ unsigned long long add2(unsigned long long a, unsigned long long b) {
    unsigned long long r;
    asm("add.rn.f32x2 %0, %1, %2;" : "=l"(r) : "l"(a), "l"(b));
    return r;
}
static __device__ __forceinline__ void up2(unsigned long long v, float& lo, float& hi) {
    unsigned ulo, uhi;
    asm("mov.b64 {%0, %1}, %2;" : "=r"(ulo), "=r"(uhi) : "l"(v));
    lo = __uint_as_float(ulo); hi = __uint_as_float(uhi);
}
static __device__ __forceinline__ float ex2f(float x) {
    float r; asm("ex2.approx.f32 %0, %1;" : "=f"(r) : "f"(x)); return r;
}
static __device__ __forceinline__ void ldmx4(uint32_t& r0, uint32_t& r1, uint32_t& r2, uint32_t& r3, uint32_t addr) {
    asm volatile("ldmatrix.sync.aligned.m8n8.x4.shared.b16 {%0,%1,%2,%3}, [%4];"
                 : "=r"(r0), "=r"(r1), "=r"(r2), "=r"(r3) : "r"(addr));
}
static __device__ __forceinline__ void mma16816(float* c, uint32_t a0, uint32_t a1, uint32_t a2, uint32_t a3,
                                                uint32_t b0, uint32_t b1) {
    asm volatile("mma.sync.aligned.m16n8k16.row.col.f32.bf16.bf16.f32 "
                 "{%0,%1,%2,%3}, {%4,%5,%6,%7}, {%8,%9}, {%0,%1,%2,%3};"
                 : "+f"(c[0]), "+f"(c[1]), "+f"(c[2]), "+f"(c[3])
                 : "r"(a0), "r"(a1), "r"(a2), "r"(a3), "r"(b0), "r"(b1));
}
// tile layout: [row][128 bf16] = 256B/row = 16 units of 16B; phys unit = u ^ (row&7)
static __device__ __forceinline__ uint32_t tphys(int row, int kbyte) {
    return (uint32_t)(row * 256 + ((((kbyte >> 4) ^ (row & 7)) << 4) | (kbyte & 15)));
}

// ---------------- kernel 1: znorm (one warp per row) ----------------
__global__ __launch_bounds__(256) void k_znorm(const float* __restrict__ z1,
                                               const float* __restrict__ z2) {
    int wid = threadIdx.x >> 5;
    int lane = threadIdx.x & 31;
    int row = blockIdx.x * 8 + wid;
    const float* zr = (row < NG) ? (z1 + (size_t)row * DF) : (z2 + (size_t)(row - NG) * DF);
    float4 v = ((const float4*)zr)[lane];
    float ss = v.x * v.x + v.y * v.y + v.z * v.z + v.w * v.w;
    #pragma unroll
    for (int off = 16; off > 0; off >>= 1)
        ss += __shfl_down_sync(0xffffffffu, ss, off);
    float inv = 1.0f / (sqrtf(__shfl_sync(0xffffffffu, ss, 0)) + 1e-8f);
    float4 o = make_float4(v.x * inv, v.y * inv, v.z * inv, v.w * inv);
    ((float4*)(g_znR + (size_t)row * DF))[lane] = o;
    int k0 = lane * 4;
    g_znT[(k0 + 0) * NSLOT + row] = o.x;
    g_znT[(k0 + 1) * NSLOT + row] = o.y;
    g_znT[(k0 + 2) * NSLOT + row] = o.z;
    g_znT[(k0 + 3) * NSLOT + row] = o.w;
}

// ---------------- kernel 2: HMMA Gram -> distances (bf16), 3 quadrants ----------------
// grid = NSLOT*3; q: 0 -> (0,0), 1 -> (0,1) [weight 2], 2 -> (1,1)
__global__ __launch_bounds__(256, 2) void k_gemm(const float* __restrict__ H1,
                                                 const float* __restrict__ H2) {
    extern __shared__ char smraw[];                 // As 32KB | Bs 32KB
    __shared__ float sqA[128], sqB[128], rsum[8];

    int bx = blockIdx.x;
    int s = bx / 3, q = bx - s * 3;
    int qr = (q == 2) ? 128 : 0;
    int qc = (q >= 1) ? 128 : 0;
    float w = (q == 1) ? 2.0f : 1.0f;
    int g = s & (NG - 1);
    const float* H = (s < NG ? H1 : H2) + (size_t)g * NPG * DF;
    int tid = threadIdx.x;
    int lane = tid & 31;
    int wid = tid >> 5;

    // ---- load both tiles as bf16 swizzled smem; sq from the same bf16 values ----
    #pragma unroll
    for (int t = 0; t < 2; t++) {
        int qoff = t ? qc : qr;
        char* base = smraw + t * 32768;
        float* sqdst = t ? sqB : sqA;
        #pragma unroll
        for (int it = 0; it < 8; it++) {
            int i = tid + it * 256;
            int row = i >> 4, u = i & 15;           // row 0..127, 16B unit 0..15
            const float4* p = (const float4*)(H + (size_t)(qoff + row) * DF + u * 8);
            float4 v0 = p[0], v1 = p[1];
            __nv_bfloat162 h0 = __floats2bfloat162_rn(v0.x, v0.y);
            __nv_bfloat162 h1 = __floats2bfloat162_rn(v0.z, v0.w);
            __nv_bfloat162 h2 = __floats2bfloat162_rn(v1.x, v1.y);
            __nv_bfloat162 h3 = __floats2bfloat162_rn(v1.z, v1.w);
            uint4 st;
            st.x = *(uint32_t*)&h0; st.y = *(uint32_t*)&h1;
            st.z = *(uint32_t*)&h2; st.w = *(uint32_t*)&h3;
            *(uint4*)(base + tphys(row, u * 16)) = st;
            float2 f0 = __bfloat1622float2(h0), f1 = __bfloat1622float2(h1);
            float2 f2 = __bfloat1622float2(h2), f3 = __bfloat1622float2(h3);
            float ssq = f0.x * f0.x + f0.y * f0.y + f1.x * f1.x + f1.y * f1.y
                      + f2.x * f2.x + f2.y * f2.y + f3.x * f3.x + f3.y * f3.y;
            ssq += __shfl_down_sync(0xffffffffu, ssq, 8, 16);
            ssq += __shfl_down_sync(0xffffffffu, ssq, 4, 16);
            ssq += __shfl_down_sync(0xffffffffu, ssq, 2, 16);
            ssq += __shfl_down_sync(0xffffffffu, ssq, 1, 16);
            if ((lane & 15) == 0) sqdst[row] = ssq;
        }
    }
    __syncthreads();

    // ---- GEMM: warp tile 32x64; warps 4x2 over 128x128 ----
    int wr = (wid >> 1) * 32;
    int wc = (wid & 1) * 64;
    uint32_t smbA = smem_u32(smraw);
    uint32_t smbB = smbA + 32768;

    float acc[2][8][4];
    #pragma unroll
    for (int mt = 0; mt < 2; mt++)
        #pragma unroll
        for (int nt = 0; nt < 8; nt++)
            #pragma unroll
            for (int e = 0; e < 4; e++) acc[mt][nt][e] = 0.f;

    int gA = lane >> 3;
    int arow_off = (gA & 1) * 8 + (lane & 7);
    int akb_off  = (gA >> 1) * 16;
    int brow_off = (gA >> 1) * 8 + (lane & 7);
    int bkb_off  = (gA & 1) * 16;

    #pragma unroll 1
    for (int ks = 0; ks < 8; ks++) {
        int kb = ks * 32;
        uint32_t a[2][4];
        #pragma unroll
        for (int mt = 0; mt < 2; mt++) {
            uint32_t addr = smbA + tphys(wr + mt * 16 + arow_off, kb + akb_off);
            ldmx4(a[mt][0], a[mt][1], a[mt][2], a[mt][3], addr);
        }
        uint32_t b[8][2];
        #pragma unroll
        for (int np = 0; np < 4; np++) {
            uint32_t addr = smbB + tphys(wc + np * 16 + brow_off, kb + bkb_off);
            uint32_t r0, r1, r2, r3;
            ldmx4(r0, r1, r2, r3, addr);
            b[np * 2][0] = r0; b[np * 2][1] = r1;
            b[np * 2 + 1][0] = r2; b[np * 2 + 1][1] = r3;
        }
        #pragma unroll
        for (int mt = 0; mt < 2; mt++)
            #pragma unroll
            for (int nt = 0; nt < 8; nt++)
                mma16816(acc[mt][nt], a[mt][0], a[mt][1], a[mt][2], a[mt][3],
                         b[nt][0], b[nt][1]);
    }

    // ---- epilogue: d = sqrt(sqi + sqj - 2G), bf16 store, partial sum ----
    float tsum = 0.f;
    int lr = lane >> 2;
    int lc = (lane & 3) * 2;
    __nv_bfloat16* Dslot = g_Dbf + ((size_t)s << 16);

    #pragma unroll
    for (int mt = 0; mt < 2; mt++) {
        int r0l = wr + mt * 16 + lr;
        float sa0 = sqA[r0l], sa1 = sqA[r0l + 8];
        int gr0 = qr + r0l;
        #pragma unroll
        for (int nt = 0; nt < 8; nt++) {
            int cl = wc + nt * 8 + lc;
            float sb0 = sqB[cl], sb1 = sqB[cl + 1];
            float* c = acc[mt][nt];
            float d00 = sqrtf(fmaxf(sa0 + sb0 - 2.0f * c[0], 0.0f) + 1e-12f);
            float d01 = sqrtf(fmaxf(sa0 + sb1 - 2.0f * c[1], 0.0f) + 1e-12f);
            float d10 = sqrtf(fmaxf(sa1 + sb0 - 2.0f * c[2], 0.0f) + 1e-12f);
            float d11 = sqrtf(fmaxf(sa1 + sb1 - 2.0f * c[3], 0.0f) + 1e-12f);
            tsum += (d00 + d01) + (d10 + d11);
            __nv_bfloat162 p0 = __floats2bfloat162_rn(d00, d01);
            __nv_bfloat162 p1 = __floats2bfloat162_rn(d10, d11);
            *(uint32_t*)(Dslot + ((size_t)gr0 << 8) + qc + cl)       = *(uint32_t*)&p0;
            *(uint32_t*)(Dslot + ((size_t)(gr0 + 8) << 8) + qc + cl) = *(uint32_t*)&p1;
        }
    }

    #pragma unroll
    for (int off = 16; off > 0; off >>= 1)
        tsum += __shfl_down_sync(0xffffffffu, tsum, off);
    if (lane == 0) rsum[wid] = tsum;
    __syncthreads();
    if (tid == 0) {
        float tot = 0.f;
        #pragma unroll
        for (int w8 = 0; w8 < 8; w8++) tot += rsum[w8];
        g_sumPart[bx] = tot * w;
    }
}

// ---------------- kernel 3: soft histogram (3 quadrants, recurrence) ----------------
__global__ __launch_bounds__(256) void k_hist() {
    int bx = blockIdx.x;
    int s = bx / 3, part = bx - s * 3;
    int qr = (part == 2) ? 128 : 0;
    int qc = (part >= 1) ? 128 : 0;
    float w = (part == 1) ? 2.0f : 1.0f;
    int tid = threadIdx.x;
    const uint4* Du4 = (const uint4*)(g_Dbf + ((size_t)s << 16));
    int ubase = (qr << 5) + (qc >> 3);

    float sumD = g_sumPart[s * 3] + g_sumPart[s * 3 + 1] + g_sumPart[s * 3 + 2];
    float mean = sumD * (1.0f / 65536.0f);
    float sbin = 5.0f / (mean + 1e-8f);

    float su_s = ex2f(2.0f * GA);
    unsigned long long su2 = pk2(su_s, su_s);

    unsigned long long acc[KBINS];
    #pragma unroll
    for (int k = 0; k < KBINS; k++) acc[k] = 0ULL;

    #pragma unroll 1
    for (int it = 0; it < 8; it++) {
        int i = it * 256 + tid;
        int r = i >> 4, u = i & 15;
        uint4 v = Du4[ubase + (r << 5) + u];          // 8 bf16 distances
        uint32_t pw[4] = {v.x, v.y, v.z, v.w};
        #pragma unroll
        for (int e = 0; e < 4; e++) {
            float2 f = __bfloat1622float2(*(__nv_bfloat162*)&pw[e]);
            float p0 = f.x * sbin, p1 = f.y * sbin;
            float t0 = p0 - 7.0f, t1 = p1 - 7.0f;
            float w70 = ex2f((GA * t0) * t0);
            float w71 = ex2f((GA * t1) * t1);
            float ru0 = ex2f(fmaf(-2.0f * GA, p0, 15.0f * GA));
            float ru1 = ex2f(fmaf(-2.0f * GA, p1, 15.0f * GA));
            float rd0 = ex2f(fmaf( 2.0f * GA, p0, -13.0f * GA));
            float rd1 = ex2f(fmaf( 2.0f * GA, p1, -13.0f * GA));
            unsigned long long w7 = pk2(w70, w71);
            unsigned long long ru = pk2(ru0, ru1);
            unsigned long long rd = pk2(rd0, rd1);

            acc[7] = add2(w7, acc[7]);
            unsigned long long wu = w7;
            #pragma unroll
            for (int k = 8; k < 16; k++) {
                wu = mul2(wu, ru);
                acc[k] = add2(wu, acc[k]);
                ru = mul2(ru, su2);
            }
            unsigned long long wd = w7;
            #pragma unroll
            for (int k = 6; k >= 0; k--) {
                wd = mul2(wd, rd);
                acc[k] = add2(wd, acc[k]);
                rd = mul2(rd, su2);
            }
        }
    }

    __shared__ float hsm[8][KBINS];
    #pragma unroll
    for (int k = 0; k < KBINS; k++) {
        float lo, hi;
        up2(acc[k], lo, hi);
        float v = lo + hi;
        #pragma unroll
        for (int off = 16; off > 0; off >>= 1)
            v += __shfl_down_sync(0xffffffffu, v, off);
        if ((tid & 31) == 0) hsm[tid >> 5][k] = v;
    }
    __syncthreads();
    if (tid < KBINS) {
        float t = 0.f;
        #pragma unroll
        for (int w8 = 0; w8 < 8; w8++) t += hsm[w8][tid];
        g_hpart[(s * 3 + part) * KBINS + tid] = t * w;
    }
}

// ---------------- kernel 4: NT-Xent (one block per row, split-k) ----------------
__global__ __launch_bounds__(256) void k_ntxent() {
    __shared__ float zr[DF];
    __shared__ float partsm[2][256];
    __shared__ float sims[256];
    __shared__ float red8[8];

    int i = blockIdx.x;
    int t = threadIdx.x;
    int lane = t & 31, wrp = t >> 5;

    if (t < 32) ((float4*)zr)[t] = ((const float4*)(g_znR + (size_t)i * DF))[t];
    __syncthreads();

    int j = t & 127, kh = t >> 7;
    const float* zp = g_znT + (size_t)(kh * 64) * NSLOT;
    const float* zlocal = zr + kh * 64;
    float a0 = 0.f, a1 = 0.f;
    #pragma unroll 8
    for (int k2 = 0; k2 < 64; k2++) {
        float zk = zlocal[k2];
        a0 += zk * zp[k2 * NSLOT + j];
        a1 += zk * zp[k2 * NSLOT + j + 128];
    }
    partsm[kh][j] = a0;
    partsm[kh][j + 128] = a1;
    __syncthreads();

    float sim = (partsm[0][t] + partsm[1][t]) * INV_TEMP;
    if (t == i) sim = -1e9f;
    sims[t] = sim;

    // block max (warp shuffle + 8-way)
    float m = sim;
    #pragma unroll
    for (int off = 16; off > 0; off >>= 1)
        m = fmaxf(m, __shfl_xor_sync(0xffffffffu, m, off));
    if (lane == 0) red8[wrp] = m;
    __syncthreads();
    float rmax = red8[0];
    #pragma unroll
    for (int w8 = 1; w8 < 8; w8++) rmax = fmaxf(rmax, red8[w8]);

    float e = __expf(sim - rmax);
    #pragma unroll
    for (int off = 16; off > 0; off >>= 1)
        e += __shfl_down_sync(0xffffffffu, e, off);
    __syncthreads();
    if (lane == 0) red8[wrp] = e;
    __syncthreads();
    if (t == 0) {
        float tot = 0.f;
        #pragma unroll
        for (int w8 = 0; w8 < 8; w8++) tot += red8[w8];
        int label = (i < NG) ? i + NG : i - NG;
        g_rowloss[i] = rmax + logf(tot) - sims[label];
    }
}

// ---------------- kernel 5: merge hists + final scalar ----------------
__global__ __launch_bounds__(256) void k_final(float* __restrict__ out) {
    __shared__ float red8[8];
    __shared__ float tsave;
    int t = threadIdx.x;
    int lane = t & 31, wrp = t >> 5;

    float v = 0.f;
    if (t < NG) {
        float h1[KBINS], h2[KBINS];
        float sA = 0.f, sB = 0.f;
        #pragma unroll
        for (int k = 0; k < KBINS; k++) {
            float a = 0.f, b = 0.f;
            #pragma unroll
            for (int p = 0; p < 3; p++) {
                a += g_hpart[(t * 3 + p) * KBINS + k];
                b += g_hpart[((t + NG) * 3 + p) * KBINS + k];
            }
            h1[k] = a; h2[k] = b; sA += a; sB += b;
        }
        float iA = 1.f / (sA + 1e-8f), iB = 1.f / (sB + 1e-8f);
        float m = 0.f;
        #pragma unroll
        for (int k = 0; k < KBINS; k++) {
            float d = h1[k] * iA - h2[k] * iB;
            m += d * d;
        }
        v = m * (1.0f / KBINS);
    }
    #pragma unroll
    for (int off = 16; off > 0; off >>= 1)
        v += __shfl_down_sync(0xffffffffu, v, off);
    if (lane == 0) red8[wrp] = v;
    __syncthreads();
    if (t == 0) {
        float tot = 0.f;
        #pragma unroll
        for (int w8 = 0; w8 < 8; w8++) tot += red8[w8];
        tsave = tot;
    }
    __syncthreads();

    float r = g_rowloss[t];
    #pragma unroll
    for (int off = 16; off > 0; off >>= 1)
        r += __shfl_down_sync(0xffffffffu, r, off);
    __syncthreads();
    if (lane == 0) red8[wrp] = r;
    __syncthreads();
    if (t == 0) {
        float tot = 0.f;
        #pragma unroll
        for (int w8 = 0; w8 < 8; w8++) tot += red8[w8];
        float topo = tsave * (1.0f / NG);
        float ntx  = tot * (1.0f / NSLOT);
        out[0] = LAMBDA * (topo + ntx);
    }
}

// ---------------- launcher ----------------
extern "C" void kernel_launch(void* const* d_in, const int* in_sizes, int n_in,
                              void* d_out, int out_size) {
    const float* H1 = (const float*)d_in[0];
    const float* H2 = (const float*)d_in[2];
    const float* z1 = (const float*)d_in[4];
    const float* z2 = (const float*)d_in[5];
    float* out = (float*)d_out;

    cudaFuncSetAttribute(k_gemm, cudaFuncAttributeMaxDynamicSharedMemorySize, 65536);

    k_znorm<<<32, 256>>>(z1, z2);
    k_gemm<<<NSLOT * 3, 256, 65536>>>(H1, H2);
    k_hist<<<NSLOT * 3, 256>>>();
    k_ntxent<<<NSLOT, 256>>>();
    k_final<<<1, 256>>>(out);
}

// round 8
// speedup vs baseline: 3.8428x; 1.2657x over previous
#include <cuda_runtime.h>
#include <cuda_bf16.h>
#include <math.h>
#include <stdint.h>

// ---------------- problem constants ----------------
#define NG    128
#define NPG   256
#define DF    128
#define KBINS 16
#define NSLOT 256

#define INV_TEMP 2.0f
#define LAMBDA   0.1f
#define GA (-0.82073318f)      // a*log2(e), a = -0.5/(0.9375^2)

// ---------------- device scratch ----------------
__device__ __nv_bfloat16 g_Dbf[(size_t)NSLOT * NPG * NPG];   // distances (3 of 4 quadrants)
__device__ float g_sumD[NSLOT];
__device__ float g_hpart[NSLOT * 3 * KBINS];
__device__ float g_rowloss[NSLOT];
__device__ float4 g_znT4[32 * NSLOT];      // [k4][row] packed 4-k chunks
__device__ float g_znR[NSLOT * DF];

// ---------------- helpers ----------------
static __device__ __forceinline__ uint32_t smem_u32(const void* p) {
    uint32_t a;
    asm("{ .reg .u64 t; cvta.to.shared.u64 t, %1; cvt.u32.u64 %0, t; }" : "=r"(a) : "l"(p));
    return a;
}
static __device__ __forceinline__ unsigned long long pk2(float lo, float hi) {
    unsigned long long r;
    asm("mov.b64 %0, {%1, %2};" : "=l"(r) : "r"(__float_as_uint(lo)), "r"(__float_as_uint(hi)));
    return r;
}
static __device__ __forceinline__ unsigned long long mul2(unsigned long long a, unsigned long long b) {
    unsigned long long r;
    asm("mul.rn.f32x2 %0, %1, %2;" : "=l"(r) : "l"(a), "l"(b));
    return r;
}
static __device__ __forceinline__ unsigned long long add2(unsigned long long a, unsigned long long b) {
    unsigned long long r;
    asm("add.rn.f32x2 %0, %1, %2;" : "=l"(r) : "l"(a), "l"(b));
    return r;
}
static __device__ __forceinline__ unsigned long long ffma2(unsigned long long a, unsigned long long b, unsigned long long c) {
    unsigned long long r;
    asm("fma.rn.f32x2 %0, %1, %2, %3;" : "=l"(r) : "l"(a), "l"(b), "l"(c));
    return r;
}
static __device__ __forceinline__ void up2(unsigned long long v, float& lo, float& hi) {
    unsigned ulo, uhi;
    asm("mov.b64 {%0, %1}, %2;" : "=r"(ulo), "=r"(uhi) : "l"(v));
    lo = __uint_as_float(ulo); hi = __uint_as_float(uhi);
}
static __device__ __forceinline__ float ex2f(float x) {
    float r; asm("ex2.approx.f32 %0, %1;" : "=f"(r) : "f"(x)); return r;
}
static __device__ __forceinline__ void ldmx4(uint32_t& r0, uint32_t& r1, uint32_t& r2, uint32_t& r3, uint32_t addr) {
    asm volatile("ldmatrix.sync.aligned.m8n8.x4.shared.b16 {%0,%1,%2,%3}, [%4];"
                 : "=r"(r0), "=r"(r1), "=r"(r2), "=r"(r3) : "r"(addr));
}
static __device__ __forceinline__ void mma16816(float* c, uint32_t a0, uint32_t a1, uint32_t a2, uint32_t a3,
                                                uint32_t b0, uint32_t b1) {
    asm volatile("mma.sync.aligned.m16n8k16.row.col.f32.bf16.bf16.f32 "
                 "{%0,%1,%2,%3}, {%4,%5,%6,%7}, {%8,%9}, {%0,%1,%2,%3};"
                 : "+f"(c[0]), "+f"(c[1]), "+f"(c[2]), "+f"(c[3])
                 : "r"(a0), "r"(a1), "r"(a2), "r"(a3), "r"(b0), "r"(b1));
}
// A tile: 256 rows x 128 bf16 = 256B/row, 16 units of 16B; phys unit = u ^ (row&7)
static __device__ __forceinline__ uint32_t tphys(int row, int kbyte) {
    return (uint32_t)(row * 256 + ((((kbyte >> 4) ^ (row & 7)) << 4) | (kbyte & 15)));
}

// ---------------- kernel 1: znorm (one warp per row) ----------------
__global__ __launch_bounds__(256) void k_znorm(const float* __restrict__ z1,
                                               const float* __restrict__ z2) {
    int wid = threadIdx.x >> 5;
    int lane = threadIdx.x & 31;
    int row = blockIdx.x * 8 + wid;
    const float* zr = (row < NG) ? (z1 + (size_t)row * DF) : (z2 + (size_t)(row - NG) * DF);
    float4 v = ((const float4*)zr)[lane];
    float ss = v.x * v.x + v.y * v.y + v.z * v.z + v.w * v.w;
    #pragma unroll
    for (int off = 16; off > 0; off >>= 1)
        ss += __shfl_down_sync(0xffffffffu, ss, off);
    float inv = 1.0f / (sqrtf(__shfl_sync(0xffffffffu, ss, 0)) + 1e-8f);
    float4 o = make_float4(v.x * inv, v.y * inv, v.z * inv, v.w * inv);
    ((float4*)(g_znR + (size_t)row * DF))[lane] = o;
    g_znT4[lane * NSLOT + row] = o;
}

// ---------------- kernel 2: HMMA Gram -> distances (bf16), one block per slot ----------------
__global__ __launch_bounds__(256, 2) void k_gemm(const float* __restrict__ H1,
                                                 const float* __restrict__ H2) {
    extern __shared__ char smraw[];                 // A: 256x128 bf16 swizzled = 64KB
    __shared__ float sq[256], rsum[8];

    int s = blockIdx.x;
    int g = s & (NG - 1);
    const float* H = (s < NG ? H1 : H2) + (size_t)g * NPG * DF;
    int tid = threadIdx.x;
    int lane = tid & 31;
    int wid = tid >> 5;

    // ---- load full H tile as bf16 swizzled smem; sq from same bf16 values ----
    #pragma unroll
    for (int it = 0; it < 16; it++) {
        int i = tid + it * 256;
        int row = i >> 4, u = i & 15;               // row 0..255, 16B unit 0..15
        const float4* p = (const float4*)(H + (size_t)row * DF + u * 8);
        float4 v0 = p[0], v1 = p[1];
        __nv_bfloat162 h0 = __floats2bfloat162_rn(v0.x, v0.y);
        __nv_bfloat162 h1 = __floats2bfloat162_rn(v0.z, v0.w);
        __nv_bfloat162 h2 = __floats2bfloat162_rn(v1.x, v1.y);
        __nv_bfloat162 h3 = __floats2bfloat162_rn(v1.z, v1.w);
        uint4 st;
        st.x = *(uint32_t*)&h0; st.y = *(uint32_t*)&h1;
        st.z = *(uint32_t*)&h2; st.w = *(uint32_t*)&h3;
        *(uint4*)(smraw + tphys(row, u * 16)) = st;
        float2 f0 = __bfloat1622float2(h0), f1 = __bfloat1622float2(h1);
        float2 f2 = __bfloat1622float2(h2), f3 = __bfloat1622float2(h3);
        float ssq = f0.x * f0.x + f0.y * f0.y + f1.x * f1.x + f1.y * f1.y
                  + f2.x * f2.x + f2.y * f2.y + f3.x * f3.x + f3.y * f3.y;
        ssq += __shfl_down_sync(0xffffffffu, ssq, 8, 16);
        ssq += __shfl_down_sync(0xffffffffu, ssq, 4, 16);
        ssq += __shfl_down_sync(0xffffffffu, ssq, 2, 16);
        ssq += __shfl_down_sync(0xffffffffu, ssq, 1, 16);
        if ((lane & 15) == 0) sq[row] = ssq;
    }
    __syncthreads();

    int wr = (wid >> 1) * 32;
    int wc = (wid & 1) * 64;
    uint32_t smb = smem_u32(smraw);

    int gA = lane >> 3;
    int arow_off = (gA & 1) * 8 + (lane & 7);
    int akb_off  = (gA >> 1) * 16;
    int brow_off = (gA >> 1) * 8 + (lane & 7);
    int bkb_off  = (gA & 1) * 16;
    int lr = lane >> 2;
    int lc = (lane & 3) * 2;
    __nv_bfloat16* Dslot = g_Dbf + ((size_t)s << 16);

    float tsum = 0.f;

    #pragma unroll 1
    for (int m = 0; m < 3; m++) {
        int qr = (m == 2) ? 128 : 0;
        int qc = (m >= 1) ? 128 : 0;
        float w = (m == 1) ? 2.0f : 1.0f;

        float acc[2][8][4];
        #pragma unroll
        for (int mt = 0; mt < 2; mt++)
            #pragma unroll
            for (int nt = 0; nt < 8; nt++)
                #pragma unroll
                for (int e = 0; e < 4; e++) acc[mt][nt][e] = 0.f;

        #pragma unroll 1
        for (int ks = 0; ks < 8; ks++) {
            int kb = ks * 32;
            uint32_t a[2][4];
            #pragma unroll
            for (int mt = 0; mt < 2; mt++) {
                uint32_t addr = smb + tphys(qr + wr + mt * 16 + arow_off, kb + akb_off);
                ldmx4(a[mt][0], a[mt][1], a[mt][2], a[mt][3], addr);
            }
            uint32_t b[8][2];
            #pragma unroll
            for (int np = 0; np < 4; np++) {
                uint32_t addr = smb + tphys(qc + wc + np * 16 + brow_off, kb + bkb_off);
                uint32_t r0, r1, r2, r3;
                ldmx4(r0, r1, r2, r3, addr);
                b[np * 2][0] = r0; b[np * 2][1] = r1;
                b[np * 2 + 1][0] = r2; b[np * 2 + 1][1] = r3;
            }
            #pragma unroll
            for (int mt = 0; mt < 2; mt++)
                #pragma unroll
                for (int nt = 0; nt < 8; nt++)
                    mma16816(acc[mt][nt], a[mt][0], a[mt][1], a[mt][2], a[mt][3],
                             b[nt][0], b[nt][1]);
        }

        float qsum = 0.f;
        #pragma unroll
        for (int mt = 0; mt < 2; mt++) {
            int r0l = qr + wr + mt * 16 + lr;
            float sa0 = sq[r0l], sa1 = sq[r0l + 8];
            #pragma unroll
            for (int nt = 0; nt < 8; nt++) {
                int cl = qc + wc + nt * 8 + lc;
                float sb0 = sq[cl], sb1 = sq[cl + 1];
                float* c = acc[mt][nt];
                float d00 = sqrtf(fmaxf(sa0 + sb0 - 2.0f * c[0], 0.0f) + 1e-12f);
                float d01 = sqrtf(fmaxf(sa0 + sb1 - 2.0f * c[1], 0.0f) + 1e-12f);
                float d10 = sqrtf(fmaxf(sa1 + sb0 - 2.0f * c[2], 0.0f) + 1e-12f);
                float d11 = sqrtf(fmaxf(sa1 + sb1 - 2.0f * c[3], 0.0f) + 1e-12f);
                qsum += (d00 + d01) + (d10 + d11);
                __nv_bfloat162 p0 = __floats2bfloat162_rn(d00, d01);
                __nv_bfloat162 p1 = __floats2bfloat162_rn(d10, d11);
                *(uint32_t*)(Dslot + ((size_t)r0l << 8) + cl)       = *(uint32_t*)&p0;
                *(uint32_t*)(Dslot + ((size_t)(r0l + 8) << 8) + cl) = *(uint32_t*)&p1;
            }
        }
        tsum = fmaf(w, qsum, tsum);
    }

    #pragma unroll
    for (int off = 16; off > 0; off >>= 1)
        tsum += __shfl_down_sync(0xffffffffu, tsum, off);
    if (lane == 0) rsum[wid] = tsum;
    __syncthreads();
    if (tid == 0) {
        float tot = 0.f;
        #pragma unroll
        for (int w8 = 0; w8 < 8; w8++) tot += rsum[w8];
        g_sumD[s] = tot;
    }
}

// ---------------- kernel 3: soft histogram (two-center recurrence) ----------------
__global__ __launch_bounds__(256) void k_hist() {
    int bx = blockIdx.x;
    int s = bx / 3, part = bx - s * 3;
    int qr = (part == 2) ? 128 : 0;
    int qc = (part >= 1) ? 128 : 0;
    float w = (part == 1) ? 2.0f : 1.0f;
    int tid = threadIdx.x;
    const uint4* Du4 = (const uint4*)(g_Dbf + ((size_t)s << 16));
    int ubase = (qr << 5) + (qc >> 3);

    float mean = g_sumD[s] * (1.0f / 65536.0f);
    float sbin = 5.0f / (mean + 1e-8f);
    unsigned long long sbin2 = pk2(sbin, sbin);

    // constants for two-center recurrence
    const unsigned long long GA2    = pk2(GA, GA);
    const unsigned long long c16GA2 = pk2(-16.0f * GA, -16.0f * GA);     // +13.13
    const unsigned long long m2GA2  = pk2(-2.0f * GA, -2.0f * GA);
    const unsigned long long p8GA2  = pk2(8.0f * GA, 8.0f * GA);
    const unsigned long long m8_2   = pk2(-8.0f, -8.0f);
    float Cs = ex2f(16.0f * GA);                                          // exp2(16*GA)
    unsigned long long C2 = pk2(Cs, Cs);

    unsigned long long acc[KBINS];
    #pragma unroll
    for (int k = 0; k < KBINS; k++) acc[k] = 0ULL;

    #pragma unroll 1
    for (int it = 0; it < 8; it++) {
        int i = it * 256 + tid;
        int r = i >> 4, u = i & 15;
        uint4 v = Du4[ubase + (r << 5) + u];          // 8 bf16 distances
        uint32_t pw[4] = {v.x, v.y, v.z, v.w};
        #pragma unroll
        for (int e = 0; e < 4; e++) {
            float2 f = __bfloat1622float2(*(__nv_bfloat162*)&pw[e]);
            unsigned long long p = mul2(pk2(f.x, f.y), sbin2);
            // lower anchor: term0 = exp2(GA*p^2 - 16GA)
            unsigned long long pg   = mul2(p, GA2);
            unsigned long long arg0 = ffma2(pg, p, c16GA2);
            // upper anchor: q = p-8; term8 = exp2(GA*q^2 - 16GA)
            unsigned long long q    = add2(p, m8_2);
            unsigned long long qg   = mul2(q, GA2);
            unsigned long long arg8 = ffma2(qg, q, c16GA2);
            // ratio: r = exp2(-2GA*p + 8GA)
            unsigned long long rarg = ffma2(p, m2GA2, p8GA2);
            float a0l, a0h, a8l, a8h, rl, rh;
            up2(arg0, a0l, a0h); up2(arg8, a8l, a8h); up2(rarg, rl, rh);
            unsigned long long t0 = pk2(ex2f(a0l), ex2f(a0h));
            unsigned long long t8 = pk2(ex2f(a8l), ex2f(a8h));
            unsigned long long rr = pk2(ex2f(rl), ex2f(rh));
            unsigned long long r2 = mul2(rr, C2);

            acc[0] = add2(acc[0], t0);
            #pragma unroll
            for (int k = 1; k < 8; k++) {
                t0 = mul2(t0, rr);
                acc[k] = add2(acc[k], t0);
            }
            acc[8] = add2(acc[8], t8);
            #pragma unroll
            for (int k = 9; k < 16; k++) {
                t8 = mul2(t8, r2);
                acc[k] = add2(acc[k], t8);
            }
        }
    }

    __shared__ float hsm[8][KBINS];
    #pragma unroll
    for (int k = 0; k < KBINS; k++) {
        int ctr = (k < 8) ? 4 : 12;
        float sc = ex2f(GA * (float)((k - ctr) * (k - ctr)));
        float lo, hi;
        up2(acc[k], lo, hi);
        float v = (lo + hi) * sc;
        #pragma unroll
        for (int off = 16; off > 0; off >>= 1)
            v += __shfl_down_sync(0xffffffffu, v, off);
        if ((tid & 31) == 0) hsm[tid >> 5][k] = v;
    }
    __syncthreads();
    if (tid < KBINS) {
        float t = 0.f;
        #pragma unroll
        for (int w8 = 0; w8 < 8; w8++) t += hsm[w8][tid];
        g_hpart[(s * 3 + part) * KBINS + tid] = t * w;
    }
}

// ---------------- kernel 4: NT-Xent (one block per row, float4 B) ----------------
__global__ __launch_bounds__(256) void k_ntxent() {
    __shared__ float4 zr4[32];
    __shared__ float sims[256];
    __shared__ float red8[8];

    int i = blockIdx.x;
    int t = threadIdx.x;
    int lane = t & 31, wrp = t >> 5;

    if (t < 32) zr4[t] = ((const float4*)(g_znR + (size_t)i * DF))[t];
    __syncthreads();

    float acc = 0.f;
    #pragma unroll
    for (int k4 = 0; k4 < 32; k4++) {
        float4 b = g_znT4[k4 * NSLOT + t];
        float4 a = zr4[k4];
        acc = fmaf(a.x, b.x, fmaf(a.y, b.y, fmaf(a.z, b.z, fmaf(a.w, b.w, acc))));
    }
    float sim = acc * INV_TEMP;
    if (t == i) sim = -1e9f;
    sims[t] = sim;

    float m = sim;
    #pragma unroll
    for (int off = 16; off > 0; off >>= 1)
        m = fmaxf(m, __shfl_xor_sync(0xffffffffu, m, off));
    if (lane == 0) red8[wrp] = m;
    __syncthreads();
    float rmax = red8[0];
    #pragma unroll
    for (int w8 = 1; w8 < 8; w8++) rmax = fmaxf(rmax, red8[w8]);

    float e = __expf(sim - rmax);
    #pragma unroll
    for (int off = 16; off > 0; off >>= 1)
        e += __shfl_down_sync(0xffffffffu, e, off);
    __syncthreads();
    if (lane == 0) red8[wrp] = e;
    __syncthreads();
    if (t == 0) {
        float tot = 0.f;
        #pragma unroll
        for (int w8 = 0; w8 < 8; w8++) tot += red8[w8];
        int label = (i < NG) ? i + NG : i - NG;
        g_rowloss[i] = rmax + logf(tot) - sims[label];
    }
}

// ---------------- kernel 5: merge hists + final scalar ----------------
__global__ __launch_bounds__(256) void k_final(float* __restrict__ out) {
    __shared__ float red8[8];
    __shared__ float tsave;
    int t = threadIdx.x;
    int lane = t & 31, wrp = t >> 5;

    float v = 0.f;
    if (t < NG) {
        float h1[KBINS], h2[KBINS];
        float sA = 0.f, sB = 0.f;
        #pragma unroll
        for (int k = 0; k < KBINS; k++) {
            float a = 0.f, b = 0.f;
            #pragma unroll
            for (int p = 0; p < 3; p++) {
                a += g_hpart[(t * 3 + p) * KBINS + k];
                b += g_hpart[((t + NG) * 3 + p) * KBINS + k];
            }
            h1[k] = a; h2[k] = b; sA += a; sB += b;
        }
        float iA = 1.f / (sA + 1e-8f), iB = 1.f / (sB + 1e-8f);
        float m = 0.f;
        #pragma unroll
        for (int k = 0; k < KBINS; k++) {
            float d = h1[k] * iA - h2[k] * iB;
            m += d * d;
        }
        v = m * (1.0f / KBINS);
    }
    #pragma unroll
    for (int off = 16; off > 0; off >>= 1)
        v += __shfl_down_sync(0xffffffffu, v, off);
    if (lane == 0) red8[wrp] = v;
    __syncthreads();
    if (t == 0) {
        float tot = 0.f;
        #pragma unroll
        for (int w8 = 0; w8 < 8; w8++) tot += red8[w8];
        tsave = tot;
    }
    __syncthreads();

    float r = g_rowloss[t];
    #pragma unroll
    for (int off = 16; off > 0; off >>= 1)
        r += __shfl_down_sync(0xffffffffu, r, off);
    __syncthreads();
    if (lane == 0) red8[wrp] = r;
    __syncthreads();
    if (t == 0) {
        float tot = 0.f;
        #pragma unroll
        for (int w8 = 0; w8 < 8; w8++) tot += red8[w8];
        float topo = tsave * (1.0f / NG);
        float ntx  = tot * (1.0f / NSLOT);
        out[0] = LAMBDA * (topo + ntx);
    }
}

// ---------------- launcher ----------------
extern "C" void kernel_launch(void* const* d_in, const int* in_sizes, int n_in,
                              void* d_out, int out_size) {
    const float* H1 = (const float*)d_in[0];
    const float* H2 = (const float*)d_in[2];
    const float* z1 = (const float*)d_in[4];
    const float* z2 = (const float*)d_in[5];
    float* out = (float*)d_out;

    cudaFuncSetAttribute(k_gemm, cudaFuncAttributeMaxDynamicSharedMemorySize, 65536);

    k_znorm<<<32, 256>>>(z1, z2);
    k_gemm<<<NSLOT, 256, 65536>>>(H1, H2);
    k_hist<<<NSLOT * 3, 256>>>();
    k_ntxent<<<NSLOT, 256>>>();
    k_final<<<1, 256>>>(out);
}